// round 2
// baseline (speedup 1.0000x reference)
#include <cuda_runtime.h>
#include <math_constants.h>

// Flash-attention style fused kernel:
//   out = softmax(p1 @ p2^T * sqrt(N2)) @ p2
// N1 = N2 = 8192, D = 128, all fp32.
//
// Round 1: pure-fp32 CUDA-core version (FFMA). Scores must be fp32-accurate
// because scale = sqrt(8192) makes the softmax near-argmax: low-precision
// scores would perturb near-tie weights by O(0.1) and blow past rel_err 1e-3.

#define N1v 8192
#define N2v 8192
#define DD  128
#define BM  64
#define BN  64
#define KVPAD 132   // row stride (floats) for q/kv tiles: (4*row + k) % 32 spreads banks
#define PPAD  68    // row stride for P tile
#define NTHREADS 256

// sqrt(8192) * log2(e) : logits computed directly in log2 domain
#define C2F 130.57784f

__global__ __launch_bounds__(NTHREADS, 2)
void attn_fwd_kernel(const float* __restrict__ P1,
                     const float* __restrict__ P2,
                     float* __restrict__ OUT)
{
    extern __shared__ float smem[];
    float* sq  = smem;                      // [BM][KVPAD]
    float* skv = sq  + BM * KVPAD;          // [BN][KVPAD]
    float* sp  = skv + BN * KVPAD;          // [BM][PPAD]

    const int t   = threadIdx.x;
    const int mr  = t >> 4;                 // 0..15  row-group id
    const int mc  = t & 15;                 // 0..15  lane within row-group
    const int r0  = mr * 4;                 // this thread's 4 rows of the tile
    const int c0  = mc * 4;                 // this thread's 4 score columns
    const int dc0 = mc * 8;                 // this thread's 8 output columns
    const int qbase = blockIdx.x * BM;

    // ---- load Q tile (BM x 128 floats = 2048 float4, 8 per thread) ----
    {
        const float4* src = (const float4*)(P1 + (size_t)qbase * DD);
        #pragma unroll
        for (int i = 0; i < 8; i++) {
            int idx = t + i * NTHREADS;       // 0..2047
            int row = idx >> 5;               // 32 float4 per row
            int c4  = idx & 31;
            float4 v = src[idx];
            *(float4*)&sq[row * KVPAD + c4 * 4] = v;
        }
    }

    // ---- running softmax state + O accumulators ----
    float m_run[4], l_run[4];
    float o[4][8];
    #pragma unroll
    for (int i = 0; i < 4; i++) {
        m_run[i] = -CUDART_INF_F;
        l_run[i] = 0.f;
        #pragma unroll
        for (int d = 0; d < 8; d++) o[i][d] = 0.f;
    }

    __syncthreads();

    for (int jb = 0; jb < N2v; jb += BN) {
        // ---- load KV tile ----
        {
            const float4* src = (const float4*)(P2 + (size_t)jb * DD);
            #pragma unroll
            for (int i = 0; i < 8; i++) {
                int idx = t + i * NTHREADS;
                int row = idx >> 5;
                int c4  = idx & 31;
                float4 v = src[idx];
                *(float4*)&skv[row * KVPAD + c4 * 4] = v;
            }
        }
        __syncthreads();

        // ---- GEMM1: acc[i][j] = q[r0+i] . kv[c0+j]  (fp32) ----
        float acc[4][4];
        #pragma unroll
        for (int i = 0; i < 4; i++)
            #pragma unroll
            for (int j = 0; j < 4; j++) acc[i][j] = 0.f;

        #pragma unroll 2
        for (int k = 0; k < DD; k += 4) {
            float4 a0 = *(const float4*)&sq[(r0 + 0) * KVPAD + k];
            float4 a1 = *(const float4*)&sq[(r0 + 1) * KVPAD + k];
            float4 a2 = *(const float4*)&sq[(r0 + 2) * KVPAD + k];
            float4 a3 = *(const float4*)&sq[(r0 + 3) * KVPAD + k];
            float4 b0 = *(const float4*)&skv[(c0 + 0) * KVPAD + k];
            float4 b1 = *(const float4*)&skv[(c0 + 1) * KVPAD + k];
            float4 b2 = *(const float4*)&skv[(c0 + 2) * KVPAD + k];
            float4 b3 = *(const float4*)&skv[(c0 + 3) * KVPAD + k];
            float4 A[4] = {a0, a1, a2, a3};
            float4 B[4] = {b0, b1, b2, b3};
            #pragma unroll
            for (int i = 0; i < 4; i++) {
                #pragma unroll
                for (int j = 0; j < 4; j++) {
                    acc[i][j] = fmaf(A[i].x, B[j].x, acc[i][j]);
                    acc[i][j] = fmaf(A[i].y, B[j].y, acc[i][j]);
                    acc[i][j] = fmaf(A[i].z, B[j].z, acc[i][j]);
                    acc[i][j] = fmaf(A[i].w, B[j].w, acc[i][j]);
                }
            }
        }

        // ---- online softmax (per row, reduced across the 16-lane row group) ----
        #pragma unroll
        for (int i = 0; i < 4; i++) {
            float mloc = fmaxf(fmaxf(acc[i][0], acc[i][1]),
                               fmaxf(acc[i][2], acc[i][3]));
            mloc *= C2F;   // logits in log2 domain: s * sqrt(N2) * log2(e)
            #pragma unroll
            for (int off = 1; off < 16; off <<= 1)
                mloc = fmaxf(mloc, __shfl_xor_sync(0xffffffffu, mloc, off));

            float mnew = fmaxf(m_run[i], mloc);
            float corr = exp2f(m_run[i] - mnew);   // exp2f(-inf) = 0 on first tile
            m_run[i] = mnew;
            l_run[i] *= corr;

            float psum = 0.f;
            #pragma unroll
            for (int j = 0; j < 4; j++) {
                float p = exp2f(fmaf(acc[i][j], C2F, -mnew));
                sp[(r0 + i) * PPAD + c0 + j] = p;
                psum += p;
            }
            #pragma unroll
            for (int off = 1; off < 16; off <<= 1)
                psum += __shfl_xor_sync(0xffffffffu, psum, off);
            l_run[i] += psum;

            #pragma unroll
            for (int d = 0; d < 8; d++) o[i][d] *= corr;
        }
        // P rows r0..r0+3 are produced entirely by this warp's 16-lane group.
        __syncwarp();

        // ---- GEMM2: o[i][*] += sum_j p[r0+i][j] * kv[j][dc0..dc0+7] ----
        #pragma unroll 2
        for (int j = 0; j < BN; j++) {
            float4 v0 = *(const float4*)&skv[j * KVPAD + dc0];
            float4 v1 = *(const float4*)&skv[j * KVPAD + dc0 + 4];
            #pragma unroll
            for (int i = 0; i < 4; i++) {
                float p = sp[(r0 + i) * PPAD + j];
                o[i][0] = fmaf(p, v0.x, o[i][0]);
                o[i][1] = fmaf(p, v0.y, o[i][1]);
                o[i][2] = fmaf(p, v0.z, o[i][2]);
                o[i][3] = fmaf(p, v0.w, o[i][3]);
                o[i][4] = fmaf(p, v1.x, o[i][4]);
                o[i][5] = fmaf(p, v1.y, o[i][5]);
                o[i][6] = fmaf(p, v1.z, o[i][6]);
                o[i][7] = fmaf(p, v1.w, o[i][7]);
            }
        }
        __syncthreads();   // before next tile overwrites skv
    }

    // ---- epilogue: normalize and store ----
    #pragma unroll
    for (int i = 0; i < 4; i++) {
        float inv = 1.0f / l_run[i];
        float4 w0, w1;
        w0.x = o[i][0] * inv; w0.y = o[i][1] * inv;
        w0.z = o[i][2] * inv; w0.w = o[i][3] * inv;
        w1.x = o[i][4] * inv; w1.y = o[i][5] * inv;
        w1.z = o[i][6] * inv; w1.w = o[i][7] * inv;
        float* dst = OUT + (size_t)(qbase + r0 + i) * DD + dc0;
        *(float4*)(dst)     = w0;
        *(float4*)(dst + 4) = w1;
    }
}

extern "C" void kernel_launch(void* const* d_in, const int* in_sizes, int n_in,
                              void* d_out, int out_size)
{
    const float* p1 = (const float*)d_in[0];
    const float* p2 = (const float*)d_in[1];
    float* out = (float*)d_out;

    const int smem_bytes = (BM * KVPAD + BN * KVPAD + BM * PPAD) * (int)sizeof(float);
    cudaFuncSetAttribute(attn_fwd_kernel,
                         cudaFuncAttributeMaxDynamicSharedMemorySize, smem_bytes);

    attn_fwd_kernel<<<N1v / BM, NTHREADS, smem_bytes>>>(p1, p2, out);
}

// round 3
// speedup vs baseline: 1.8662x; 1.8662x over previous
#include <cuda_runtime.h>
#include <math_constants.h>

// Flash-attention style fused kernel:
//   out = softmax(p1 @ p2^T * sqrt(N2)) @ p2
// N1 = N2 = 8192, D = 128, all fp32.
//
// Round 2: packed f32x2 FMA (fma.rn.f32x2) in both GEMMs + bank-conflict-aware
// lane->data remapping so the smem crossbar (128 B/cyc/SM) stays below the
// doubled math rate. Scores remain exact fp32 (softmax near-argmax, scale
// sqrt(8192) makes low-precision scores fail rel_err 1e-3).

#define N1v 8192
#define N2v 8192
#define DD  128
#define BM  64
#define BN  64
#define KVPAD 132   // row stride (floats); 132*4 % 32 banks => lane-row stride 4mc: 2-way min
#define PPAD  68    // row stride for P tile (16B aligned rows)
#define NTHREADS 256

// sqrt(8192) * log2(e) : logits computed directly in log2 domain
#define C2F 130.57784f

// packed f32x2 ops (ptxas never auto-fuses these from C++)
#define FMA2(d, a, b) asm("fma.rn.f32x2 %0, %1, %2, %0;" : "+l"(d) : "l"(a), "l"(b))
#define MUL2(d, s)    asm("mul.rn.f32x2 %0, %0, %1;"     : "+l"(d) : "l"(s))
#define PACK2(d, x, y) asm("mov.b64 %0, {%1, %2};" : "=l"(d) : "f"(x), "f"(y))
#define UNPACK2(lo, hi, v) asm("mov.b64 {%0, %1}, %2;" : "=f"(lo), "=f"(hi) : "l"(v))

__global__ __launch_bounds__(NTHREADS, 1)
void attn_fwd_kernel(const float* __restrict__ P1,
                     const float* __restrict__ P2,
                     float* __restrict__ OUT)
{
    extern __shared__ float smem[];
    float* sq  = smem;                      // [BM][KVPAD]
    float* skv = sq  + BM * KVPAD;          // [BN][KVPAD]
    float* sp  = skv + BN * KVPAD;          // [BM][PPAD]

    const int t   = threadIdx.x;
    const int mr  = t >> 4;                 // 0..15  row-group id
    const int mc  = t & 15;                 // 0..15  lane within row-group
    const int r0  = mr * 4;                 // this thread's 4 score/output rows
    // GEMM1: this thread owns score columns {mc + 16*jj}, jj=0..3
    // GEMM2: this thread owns output cols {4mc..4mc+3} and {64+4mc..64+4mc+3}
    const int dcA = 4 * mc;
    const int dcB = 64 + 4 * mc;
    const int qbase = blockIdx.x * BM;

    // ---- load Q tile (BM x 128 floats = 2048 float4, 8 per thread) ----
    {
        const float4* src = (const float4*)(P1 + (size_t)qbase * DD);
        #pragma unroll
        for (int i = 0; i < 8; i++) {
            int idx = t + i * NTHREADS;       // 0..2047
            int row = idx >> 5;               // 32 float4 per row
            int c4  = idx & 31;
            float4 v = src[idx];
            *(float4*)&sq[row * KVPAD + c4 * 4] = v;
        }
    }

    // ---- running softmax state + packed O accumulators ----
    float m_run[4], l_run[4];
    unsigned long long o2[4][4];            // 4 rows x 4 col-pairs (8 cols)
    #pragma unroll
    for (int i = 0; i < 4; i++) {
        m_run[i] = -CUDART_INF_F;
        l_run[i] = 0.f;
        #pragma unroll
        for (int d = 0; d < 4; d++) o2[i][d] = 0ull;
    }

    __syncthreads();

    for (int jb = 0; jb < N2v; jb += BN) {
        // ---- load KV tile ----
        {
            const float4* src = (const float4*)(P2 + (size_t)jb * DD);
            #pragma unroll
            for (int i = 0; i < 8; i++) {
                int idx = t + i * NTHREADS;
                int row = idx >> 5;
                int c4  = idx & 31;
                float4 v = src[idx];
                *(float4*)&skv[row * KVPAD + c4 * 4] = v;
            }
        }
        __syncthreads();

        // ---- GEMM1 (packed k-pairs): acc2[i][jj] lanes hold (even-k, odd-k)
        //      partial sums of q[r0+i] . kv[mc+16*jj] ----
        unsigned long long acc2[4][4];
        #pragma unroll
        for (int i = 0; i < 4; i++)
            #pragma unroll
            for (int j = 0; j < 4; j++) acc2[i][j] = 0ull;

        #pragma unroll 2
        for (int k = 0; k < DD; k += 4) {
            ulonglong2 A[4], B[4];
            #pragma unroll
            for (int i = 0; i < 4; i++)       // broadcast within the 16-lane group
                A[i] = *(const ulonglong2*)&sq[(r0 + i) * KVPAD + k];
            #pragma unroll
            for (int j = 0; j < 4; j++)       // lane-varying rows: 2-way min conflicts
                B[j] = *(const ulonglong2*)&skv[(mc + 16 * j) * KVPAD + k];
            #pragma unroll
            for (int i = 0; i < 4; i++) {
                #pragma unroll
                for (int j = 0; j < 4; j++) {
                    FMA2(acc2[i][j], A[i].x, B[j].x);
                    FMA2(acc2[i][j], A[i].y, B[j].y);
                }
            }
        }

        // ---- online softmax (per row, reduced across the 16-lane row group) ----
        #pragma unroll
        for (int i = 0; i < 4; i++) {
            float s[4];
            #pragma unroll
            for (int j = 0; j < 4; j++) {
                float lo, hi;
                UNPACK2(lo, hi, acc2[i][j]);
                s[j] = lo + hi;
            }
            float mloc = fmaxf(fmaxf(s[0], s[1]), fmaxf(s[2], s[3]));
            mloc *= C2F;   // logits in log2 domain: s * sqrt(N2) * log2(e)
            #pragma unroll
            for (int off = 1; off < 16; off <<= 1)
                mloc = fmaxf(mloc, __shfl_xor_sync(0xffffffffu, mloc, off));

            float mnew = fmaxf(m_run[i], mloc);
            float corr = exp2f(m_run[i] - mnew);   // exp2f(-inf) = 0 on first tile
            m_run[i] = mnew;
            l_run[i] *= corr;

            float psum = 0.f;
            #pragma unroll
            for (int j = 0; j < 4; j++) {
                float p = exp2f(fmaf(s[j], C2F, -mnew));
                sp[(r0 + i) * PPAD + mc + 16 * j] = p;
                psum += p;
            }
            #pragma unroll
            for (int off = 1; off < 16; off <<= 1)
                psum += __shfl_xor_sync(0xffffffffu, psum, off);
            l_run[i] += psum;

            unsigned long long corr2;
            PACK2(corr2, corr, corr);
            #pragma unroll
            for (int d = 0; d < 4; d++) MUL2(o2[i][d], corr2);
        }
        // P rows r0..r0+3 are produced entirely by this warp's 16-lane group.
        __syncwarp();

        // ---- GEMM2 (packed col-pairs): o2[i][.] += p[r0+i][j] * kv[j][cols] ----
        #pragma unroll 1
        for (int jb4 = 0; jb4 < BN; jb4 += 4) {
            float4 P4[4];
            #pragma unroll
            for (int i = 0; i < 4; i++)       // broadcast (2 unique per warp)
                P4[i] = *(const float4*)&sp[(r0 + i) * PPAD + jb4];
            #pragma unroll
            for (int jj = 0; jj < 4; jj++) {
                int jr = jb4 + jj;
                // 16B chunks at byte stride 16 across lanes: 2-way (minimum)
                ulonglong2 vA = *(const ulonglong2*)&skv[jr * KVPAD + dcA];
                ulonglong2 vB = *(const ulonglong2*)&skv[jr * KVPAD + dcB];
                #pragma unroll
                for (int i = 0; i < 4; i++) {
                    const float* pf = (const float*)&P4[i];
                    float pv = pf[jj];
                    unsigned long long pp;
                    PACK2(pp, pv, pv);
                    FMA2(o2[i][0], pp, vA.x);
                    FMA2(o2[i][1], pp, vA.y);
                    FMA2(o2[i][2], pp, vB.x);
                    FMA2(o2[i][3], pp, vB.y);
                }
            }
        }
        __syncthreads();   // before next tile overwrites skv
    }

    // ---- epilogue: normalize and store ----
    #pragma unroll
    for (int i = 0; i < 4; i++) {
        float inv = 1.0f / l_run[i];
        float f[8];
        #pragma unroll
        for (int d = 0; d < 4; d++) {
            float lo, hi;
            UNPACK2(lo, hi, o2[i][d]);
            f[2 * d]     = lo * inv;
            f[2 * d + 1] = hi * inv;
        }
        float* dst = OUT + (size_t)(qbase + r0 + i) * DD;
        float4 wA = make_float4(f[0], f[1], f[2], f[3]);
        float4 wB = make_float4(f[4], f[5], f[6], f[7]);
        *(float4*)(dst + dcA) = wA;
        *(float4*)(dst + dcB) = wB;
    }
}

extern "C" void kernel_launch(void* const* d_in, const int* in_sizes, int n_in,
                              void* d_out, int out_size)
{
    const float* p1 = (const float*)d_in[0];
    const float* p2 = (const float*)d_in[1];
    float* out = (float*)d_out;

    const int smem_bytes = (BM * KVPAD + BN * KVPAD + BM * PPAD) * (int)sizeof(float);
    cudaFuncSetAttribute(attn_fwd_kernel,
                         cudaFuncAttributeMaxDynamicSharedMemorySize, smem_bytes);

    attn_fwd_kernel<<<N1v / BM, NTHREADS, smem_bytes>>>(p1, p2, out);
}